// round 12
// baseline (speedup 1.0000x reference)
#include <cuda_runtime.h>
#include <cuda_bf16.h>
#include <mma.h>
#include <cstdint>

// ============================================================================
// VQ forward v12: int8 IMMA approx GEMM (exact s32 accumulation; only input
// quantization error) -> int-margin candidate filter -> exact fp32 rescore.
// Exact-bits contract (validated R7/R10/R11): d = fl(fl(a_n+b_k) - 2C),
// C = ascending-k single-accumulator fp32 FFMA chain, ties -> lowest index.
// ============================================================================

namespace vq12 {
using namespace nvcuda;

constexpr int DIM  = 512;
constexpr int KCNT = 8192;
constexpr int NTOK = 32768;
constexpr int BM   = 128;
constexpr int BN   = 128;
constexpr int CAP  = 256;

// int8 quantization scales (cover |z|<=6.2, |e|<=0.0285; max over data ~5.6s)
constexpr float INV_SA = 127.0f / 6.2f;
constexpr float INV_SB = 127.0f / 0.0285f;
constexpr int   MARGIN_I = 8000;     // ~0.088 in C units = ~44 sigma of dot err

constexpr int LDA = 528;             // s8 row stride (512 + 16)
constexpr int LDB = 80;              // s8 row stride (64 + 16)
constexpr int LDC = 136;             // s32 row stride (128 + 8)
constexpr int BK  = 64;              // k per staged chunk
constexpr int NBUF = 4;
constexpr int BUFSZ = BN * LDB;      // 10240 B
constexpr int SM_AS = 0;                          // 128*528      = 67584
constexpr int SM_BS = SM_AS + BM * LDA;           // 4*10240      = 40960
constexpr int SM_CS = SM_BS + NBUF * BUFSZ;       // 128*136*4    = 69632
constexpr int SM_TOT = SM_CS + BM * LDC * 4;      // 178176 B

__device__ float g_nrm[KCNT + NTOK];   // [0,KCNT): ||e||^2 ; rest: ||z||^2
__device__ int   g_sel[NTOK];
__device__ float g_prt[NTOK];
__device__ signed char g_emb8[KCNT * DIM];
__device__ int   g_cnt[NTOK];
__device__ int   g_cand[(size_t)NTOK * CAP];
__device__ int   g_cvalI[(size_t)NTOK * CAP];

// ----------------- cp.async helpers (baseline ISA) -------------------------
__device__ __forceinline__ void cp_async16(void* dst_smem, const void* src) {
    uint32_t d = (uint32_t)__cvta_generic_to_shared(dst_smem);
    asm volatile("cp.async.ca.shared.global [%0], [%1], 16;" :: "r"(d), "l"(src));
}
__device__ __forceinline__ void cp_commit() {
    asm volatile("cp.async.commit_group;" ::: "memory");
}
template <int N>
__device__ __forceinline__ void cp_wait() {
    asm volatile("cp.async.wait_group %0;" :: "n"(N) : "memory");
}
__device__ __forceinline__ signed char q8(float x, float inv) {
    int q = __float2int_rn(x * inv);
    q = max(-127, min(127, q));
    return (signed char)q;
}

// ---------------------------------------------------------------------------
// Exact fp32 row norms (validated; order argmin-irrelevant).
// ---------------------------------------------------------------------------
__global__ void norms_fused(const float* __restrict__ emb,
                            const float* __restrict__ z) {
    const int gw = (blockIdx.x * 256 + threadIdx.x) >> 5;
    const int lane = threadIdx.x & 31;
    const float* src = (gw < KCNT) ? (emb + (size_t)gw * DIM)
                                   : (z + (size_t)(gw - KCNT) * DIM);
    float acc = 0.f;
    #pragma unroll
    for (int j = 0; j < DIM / 32; j++) {
        float v = src[lane + (j << 5)];
        acc = __fadd_rn(acc, __fmul_rn(v, v));
    }
    #pragma unroll
    for (int sh = 16; sh; sh >>= 1)
        acc = __fadd_rn(acc, __shfl_down_sync(0xffffffffu, acc, sh));
    if (lane == 0) g_nrm[gw] = acc;
}

// emb fp32 -> s8 (deterministic rn quantization).
__global__ void prep(const float* __restrict__ emb) {
    const int i = blockIdx.x * 256 + threadIdx.x;   // [0, 1048576), 4 elems each
    float4 v = reinterpret_cast<const float4*>(emb)[i];
    char4 c;
    c.x = q8(v.x, INV_SB); c.y = q8(v.y, INV_SB);
    c.z = q8(v.z, INV_SB); c.w = q8(v.w, INV_SB);
    reinterpret_cast<char4*>(g_emb8)[i] = c;
}

// ---------------------------------------------------------------------------
// Approx pass: wmma int8 (IMMA). CTA = 128 z rows (s8, resident). 8 warps
// (4m x 2n), warp tile 32x64. K chunked by 64; 4-buffer cp.async pipeline,
// ONE __syncthreads per chunk. Epilogue: s32 C -> smem, per-row running max
// + int-margin candidate push (single writer per row).
// ---------------------------------------------------------------------------
__global__ __launch_bounds__(256, 1)
void tc_pass(const float* __restrict__ z) {
    extern __shared__ char smraw[];
    signed char* As = reinterpret_cast<signed char*>(smraw + SM_AS);
    signed char* Bs = reinterpret_cast<signed char*>(smraw + SM_BS);
    int*         Cs = reinterpret_cast<int*>(smraw + SM_CS);

    const int tid = threadIdx.x;
    const int wid = tid >> 5;
    const int wm  = wid & 3;
    const int wn  = wid >> 2;
    const int row0 = blockIdx.x * BM;

    // Stage A: quantize this CTA's z rows to s8 row-major [128][LDA].
    for (int i = tid; i < BM * 128; i += 256) {        // 4 elems per slot
        const int r = i >> 7, c4 = (i & 127) << 2;
        float4 v = *reinterpret_cast<const float4*>(z + (size_t)(row0 + r) * DIM + c4);
        char4 c;
        c.x = q8(v.x, INV_SA); c.y = q8(v.y, INV_SA);
        c.z = q8(v.z, INV_SA); c.w = q8(v.w, INV_SA);
        *reinterpret_cast<char4*>(As + r * LDA + c4) = c;
    }
    __syncthreads();

    int runmaxI = 0x80000000;
    int ccnt    = 0;

    for (int ct = 0; ct < KCNT / BN; ct++) {
        const int col0 = ct * BN;
        const signed char* ebase = g_emb8 + (size_t)col0 * DIM;

        wmma::fragment<wmma::accumulator, 16, 16, 16, int> acc[2][4];
        #pragma unroll
        for (int i = 0; i < 2; i++)
            #pragma unroll
            for (int j = 0; j < 4; j++) wmma::fill_fragment(acc[i][j], 0);

        // prologue: chunks 0,1 -> buffers 0,1. Chunk = 128 rows x 64B = 512x16B.
        #pragma unroll
        for (int s = 0; s < 2; s++) {
            #pragma unroll
            for (int i = tid; i < 512; i += 256) {
                const int r = i >> 2, p = (i & 3) << 4;
                cp_async16(Bs + s * BUFSZ + r * LDB + p, ebase + (size_t)r * DIM + s * BK + p);
            }
            cp_commit();
        }

        #pragma unroll
        for (int kc = 0; kc < DIM / BK; kc++) {        // 8 chunks
            if (kc + 2 < DIM / BK) {
                const int b = (kc + 2) & (NBUF - 1);
                #pragma unroll
                for (int i = tid; i < 512; i += 256) {
                    const int r = i >> 2, p = (i & 3) << 4;
                    cp_async16(Bs + b * BUFSZ + r * LDB + p,
                               ebase + (size_t)r * DIM + (kc + 2) * BK + p);
                }
                cp_commit();
                cp_wait<2>();
            } else if (kc + 2 == DIM / BK) {
                cp_wait<1>();
            } else {
                cp_wait<0>();
            }
            __syncthreads();

            const signed char* bb = Bs + (kc & (NBUF - 1)) * BUFSZ;
            #pragma unroll
            for (int ks = 0; ks < BK / 16; ks++) {
                wmma::fragment<wmma::matrix_a, 16, 16, 16, signed char, wmma::row_major> af[2];
                wmma::fragment<wmma::matrix_b, 16, 16, 16, signed char, wmma::col_major> bf[4];
                #pragma unroll
                for (int i = 0; i < 2; i++)
                    wmma::load_matrix_sync(af[i],
                        As + (wm * 32 + i * 16) * LDA + kc * BK + ks * 16, LDA);
                #pragma unroll
                for (int j = 0; j < 4; j++)
                    wmma::load_matrix_sync(bf[j],
                        bb + (wn * 64 + j * 16) * LDB + ks * 16, LDB);
                #pragma unroll
                for (int i = 0; i < 2; i++)
                    #pragma unroll
                    for (int j = 0; j < 4; j++)
                        wmma::mma_sync(acc[i][j], af[i], bf[j], acc[i][j]);
            }
        }
        __syncthreads();   // all MMA consumers done before C overwrites smem

        // C block (s32) -> smem
        #pragma unroll
        for (int i = 0; i < 2; i++)
            #pragma unroll
            for (int j = 0; j < 4; j++)
                wmma::store_matrix_sync(
                    Cs + (wm * 32 + i * 16) * LDC + wn * 64 + j * 16,
                    acc[i][j], LDC, wmma::mem_row_major);
        __syncthreads();

        // Per-row running max + margin candidate push.
        if (tid < BM) {
            const int4* cr = reinterpret_cast<const int4*>(Cs + tid * LDC);
            int mx = runmaxI;
            #pragma unroll
            for (int q = 0; q < 32; q++) {
                const int4 v = cr[q];
                mx = max(mx, max(max(v.x, v.y), max(v.z, v.w)));
            }
            runmaxI = mx;
            const int thr = mx - MARGIN_I;
            const int rowG = row0 + tid;
            const size_t base = (size_t)rowG * CAP;
            #pragma unroll
            for (int q = 0; q < 32; q++) {
                const int4 v = cr[q];
                const int kb = col0 + 4 * q;
                if (v.x >= thr) { if (ccnt < CAP) { g_cand[base+ccnt]=kb;   g_cvalI[base+ccnt]=v.x; } ccnt++; }
                if (v.y >= thr) { if (ccnt < CAP) { g_cand[base+ccnt]=kb+1; g_cvalI[base+ccnt]=v.y; } ccnt++; }
                if (v.z >= thr) { if (ccnt < CAP) { g_cand[base+ccnt]=kb+2; g_cvalI[base+ccnt]=v.z; } ccnt++; }
                if (v.w >= thr) { if (ccnt < CAP) { g_cand[base+ccnt]=kb+3; g_cvalI[base+ccnt]=v.w; } ccnt++; }
            }
        }
        __syncthreads();
    }
    if (tid < BM) g_cnt[row0 + tid] = ccnt;
}

// ---------------------------------------------------------------------------
// Exact rescore: warp per row, candidate per lane. Identical fp32 chain to
// the validated kernels; int-domain prune against global candidate max.
// ---------------------------------------------------------------------------
__device__ __forceinline__ void exact_score(const float4* __restrict__ zr,
                                            const float* __restrict__ emb,
                                            float an, int k,
                                            float& bv, int& bi) {
    const float4* er = reinterpret_cast<const float4*>(emb + (size_t)k * DIM);
    float acc = 0.f;
    #pragma unroll 8
    for (int q = 0; q < DIM / 4; q++) {
        const float4 a = zr[q], b = er[q];
        acc = __fmaf_rn(a.x, b.x, acc);
        acc = __fmaf_rn(a.y, b.y, acc);
        acc = __fmaf_rn(a.z, b.z, acc);
        acc = __fmaf_rn(a.w, b.w, acc);
    }
    const float t = __fadd_rn(an, g_nrm[k]);
    const float v = __fmaf_rn(-2.f, acc, t);
    if (v < bv || (v == bv && k < bi)) { bv = v; bi = k; }
}

__global__ void rescore(const float* __restrict__ z, const float* __restrict__ emb) {
    const int n    = (blockIdx.x * 256 + threadIdx.x) >> 5;
    const int lane = threadIdx.x & 31;
    if (n >= NTOK) return;
    const float an = g_nrm[KCNT + n];
    const float4* zr = reinterpret_cast<const float4*>(z + (size_t)n * DIM);
    const int cnt = g_cnt[n];
    float bv = 3.4e38f;
    int   bi = 0x7fffffff;

    if (cnt > CAP) {                    // fallback: exact full scan
        for (int k = lane; k < KCNT; k += 32)
            exact_score(zr, emb, an, k, bv, bi);
    } else {
        const size_t base = (size_t)n * CAP;
        int cmax = 0x80000000;
        for (int s = lane; s < cnt; s += 32) cmax = max(cmax, g_cvalI[base + s]);
        #pragma unroll
        for (int o = 16; o; o >>= 1)
            cmax = max(cmax, __shfl_xor_sync(0xffffffffu, cmax, o));
        const int thr = cmax - MARGIN_I;
        for (int s = lane; s < cnt; s += 32) {
            if (g_cvalI[base + s] < thr) continue;
            exact_score(zr, emb, an, g_cand[base + s], bv, bi);
        }
    }
    #pragma unroll
    for (int o = 16; o; o >>= 1) {
        const float v2 = __shfl_xor_sync(0xffffffffu, bv, o);
        const int   i2 = __shfl_xor_sync(0xffffffffu, bi, o);
        if (v2 < bv || (v2 == bv && i2 < bi)) { bv = v2; bi = i2; }
    }
    if (lane == 0) g_sel[n] = bi;
}

// ---------------------------------------------------------------------------
__global__ void finalize(const float* __restrict__ z, const float* __restrict__ emb,
                         float* __restrict__ out, int N) {
    const int half = threadIdx.x >> 7;
    const int lt   = threadIdx.x & 127;
    const int n    = blockIdx.x * 2 + half;
    const int k    = g_sel[n];
    const float* zr = z + (size_t)n * DIM;
    const float* er = emb + (size_t)k * DIM;
    float* o = out + 1 + (size_t)n * DIM;
    float s = 0.f;
    #pragma unroll
    for (int j = 0; j < DIM / 128; j++) {
        const int c = lt + j * 128;
        const float zv = zr[c];
        const float dx = __fadd_rn(er[c], -zv);
        o[c] = __fadd_rn(zv, dx);
        s = __fmaf_rn(dx, dx, s);
    }
    #pragma unroll
    for (int sh = 16; sh; sh >>= 1) s += __shfl_down_sync(0xffffffffu, s, sh);
    __shared__ float ws[8];
    if ((lt & 31) == 0) ws[half * 4 + (lt >> 5)] = s;
    __syncthreads();
    if (lt == 0) {
        g_prt[n] = ws[half*4] + ws[half*4+1] + ws[half*4+2] + ws[half*4+3];
        out[1 + (size_t)N * DIM + n] = (float)k;
    }
}

__global__ void reduce_loss(float* __restrict__ out, int N) {
    __shared__ float sm[512];
    float s = 0.f;
    for (int i = threadIdx.x; i < N; i += 512) s += g_prt[i];
    sm[threadIdx.x] = s;
    __syncthreads();
    for (int o = 256; o; o >>= 1) {
        if (threadIdx.x < o) sm[threadIdx.x] += sm[threadIdx.x + o];
        __syncthreads();
    }
    if (threadIdx.x == 0) out[0] = 2.f * sm[0] / ((float)N * (float)DIM);
}

}  // namespace vq12

// ----------------------------------------------------------------------------
extern "C" void kernel_launch(void* const* d_in, const int* in_sizes, int n_in,
                              void* d_out, int out_size) {
    using namespace vq12;
    const float* z   = (const float*)d_in[0];
    const float* emb = (const float*)d_in[1];
    float* out = (float*)d_out;
    const int N = in_sizes[0] / DIM;    // 32768

    cudaFuncSetAttribute(tc_pass, cudaFuncAttributeMaxDynamicSharedMemorySize, SM_TOT);

    norms_fused<<<(KCNT + N) / 8, 256>>>(emb, z);
    prep<<<KCNT * DIM / 4 / 256, 256>>>(emb);
    tc_pass<<<N / BM, 256, SM_TOT>>>(z);
    rescore<<<N * 32 / 256, 256>>>(z, emb);
    finalize<<<N / 2, 256>>>(z, emb, out, N);
    reduce_loss<<<1, 512>>>(out, N);
}

// round 15
// speedup vs baseline: 2.9781x; 2.9781x over previous
#include <cuda_runtime.h>
#include <cuda_bf16.h>
#include <cstdint>

// ============================================================================
// VQ forward v15: v14 with the B-fragment ldmatrix FIXED (non-trans, n-row
// addressing, {r0,r2}/{r1,r3} pairing). Raw mma.sync bf16 approx GEMM ->
// margin candidate filter -> exact fp32 warp-parallel rescore.
// Exact-bits contract (validated R7/R10/R11): d = fl(fl(a_n+b_k) - 2C),
// C = ascending-k single-accumulator fp32 FFMA chain, ties -> lowest index.
// ============================================================================

namespace vq15 {

constexpr int DIM  = 512;
constexpr int KCNT = 8192;
constexpr int NTOK = 32768;
constexpr int BM   = 128;
constexpr int BN   = 128;
constexpr int CAP  = 256;
constexpr float MARGIN = 0.032f;   // >= 2*bf16 dot bound (0.0107) + quantum

constexpr int LDA = 520;           // bf16 (512+8): ldmatrix A rows r%8 distinct
constexpr int LDB = 40;            // bf16 (32+8):  B rows 5n%8 distinct
constexpr int LDC = 72;            // f32  (64+8), epilogue split in 2 phases
constexpr int BK  = 32;
constexpr int NBUF = 4;
constexpr int BUFSZ = BN * LDB * 2;               // 10240 B
constexpr int SM_AS = 0;                          // 128*520*2 = 133120
constexpr int SM_BS = SM_AS + BM * LDA * 2;       // 4*10240   =  40960
constexpr int SM_CS = SM_BS + NBUF * BUFSZ;       // 128*72*4  =  36864
constexpr int SM_TOT = SM_CS + BM * LDC * 4;      // 210944 B

__device__ float g_nrm[KCNT + NTOK];   // [0,KCNT): ||e||^2 ; rest: ||z||^2
__device__ int   g_sel[NTOK];
__device__ float g_prt[NTOK];
__device__ __nv_bfloat16 g_embh[KCNT * DIM];
__device__ int   g_cnt[NTOK];
__device__ int   g_cand[(size_t)NTOK * CAP];
__device__ float g_cval[(size_t)NTOK * CAP];

// ----------------- PTX helpers (baseline ISA) -------------------------------
__device__ __forceinline__ void cp_async16(uint32_t dst, const void* src) {
    asm volatile("cp.async.ca.shared.global [%0], [%1], 16;" :: "r"(dst), "l"(src));
}
__device__ __forceinline__ void cp_commit() {
    asm volatile("cp.async.commit_group;" ::: "memory");
}
template <int N>
__device__ __forceinline__ void cp_wait() {
    asm volatile("cp.async.wait_group %0;" :: "n"(N) : "memory");
}
__device__ __forceinline__ void ldsm4(uint32_t* r, uint32_t a) {
    asm volatile("ldmatrix.sync.aligned.m8n8.x4.shared.b16 {%0,%1,%2,%3}, [%4];"
                 : "=r"(r[0]), "=r"(r[1]), "=r"(r[2]), "=r"(r[3]) : "r"(a));
}
__device__ __forceinline__ void mma16816(float* c, const uint32_t* a,
                                         uint32_t b0, uint32_t b1) {
    asm volatile(
        "mma.sync.aligned.m16n8k16.row.col.f32.bf16.bf16.f32 "
        "{%0,%1,%2,%3}, {%4,%5,%6,%7}, {%8,%9}, {%0,%1,%2,%3};"
        : "+f"(c[0]), "+f"(c[1]), "+f"(c[2]), "+f"(c[3])
        : "r"(a[0]), "r"(a[1]), "r"(a[2]), "r"(a[3]), "r"(b0), "r"(b1));
}

// ---------------------------------------------------------------------------
// Exact fp32 row norms (validated; order argmin-irrelevant).
// ---------------------------------------------------------------------------
__global__ void norms_fused(const float* __restrict__ emb,
                            const float* __restrict__ z) {
    const int gw = (blockIdx.x * 256 + threadIdx.x) >> 5;
    const int lane = threadIdx.x & 31;
    const float* src = (gw < KCNT) ? (emb + (size_t)gw * DIM)
                                   : (z + (size_t)(gw - KCNT) * DIM);
    float acc = 0.f;
    #pragma unroll
    for (int j = 0; j < DIM / 32; j++) {
        float v = src[lane + (j << 5)];
        acc = __fadd_rn(acc, __fmul_rn(v, v));
    }
    #pragma unroll
    for (int sh = 16; sh; sh >>= 1)
        acc = __fadd_rn(acc, __shfl_down_sync(0xffffffffu, acc, sh));
    if (lane == 0) g_nrm[gw] = acc;
}

// emb fp32 -> bf16 (rn).
__global__ void prep(const float* __restrict__ emb) {
    const int i = blockIdx.x * 256 + threadIdx.x;   // [0, 1048576)
    float4 v = reinterpret_cast<const float4*>(emb)[i];
    reinterpret_cast<__nv_bfloat162*>(g_embh)[2*i]   = __floats2bfloat162_rn(v.x, v.y);
    reinterpret_cast<__nv_bfloat162*>(g_embh)[2*i+1] = __floats2bfloat162_rn(v.z, v.w);
}

// ---------------------------------------------------------------------------
// Approx pass: raw mma.sync bf16. CTA = 128 z rows resident (bf16). 8 warps
// (4m x 2n), warp tile 32x64. K chunked by 32, 4-buffer cp.async pipeline,
// ONE barrier per chunk. Register epilogue -> Cs smem in two 64-col phases ->
// per-row running max + margin push.
// B fragments: ldmatrix NON-trans; lane addr row = n0+(lane&15), k-half by
// lane>>4; per n16 load, n8-low operand = {r0,r2}, n8-high = {r1,r3}.
// ---------------------------------------------------------------------------
__global__ __launch_bounds__(256, 1)
void tc_pass(const float* __restrict__ z) {
    extern __shared__ char smraw[];
    __nv_bfloat16* As = reinterpret_cast<__nv_bfloat16*>(smraw + SM_AS);
    float*         Cs = reinterpret_cast<float*>(smraw + SM_CS);
    const uint32_t smA = (uint32_t)__cvta_generic_to_shared(smraw + SM_AS);
    const uint32_t smB = (uint32_t)__cvta_generic_to_shared(smraw + SM_BS);

    const int tid  = threadIdx.x;
    const int wid  = tid >> 5;
    const int lane = tid & 31;
    const int wm   = wid & 3;          // 4 m-groups of 32 rows
    const int wn   = wid >> 2;         // 2 n-groups of 64 cols
    const int row0 = blockIdx.x * BM;

    // Stage A: z rows -> bf16 row-major [128][LDA].
    for (int i = tid; i < BM * 256; i += 256) {
        const int r = i >> 8, c2 = i & 255;
        float2 f = *reinterpret_cast<const float2*>(z + (size_t)(row0 + r) * DIM + 2 * c2);
        *reinterpret_cast<__nv_bfloat162*>(As + r * LDA + 2 * c2) =
            __floats2bfloat162_rn(f.x, f.y);
    }
    __syncthreads();

    // ldmatrix lane address bases (bytes).
    const uint32_t aBase = smA +
        (uint32_t)(((wm * 32 + (lane & 15)) * LDA + ((lane >> 4) << 3)) * 2);
    // B: row = warp n-group base + (lane&15); k-half = (lane>>4)*8.
    const uint32_t bLaneOff =
        (uint32_t)(((wn * 64 + (lane & 15)) * LDB + ((lane >> 4) << 3)) * 2);

    // cp.async staging: 2 x 16B per thread per chunk (rows n, 64B each).
    const int csR0 = tid >> 1;                   // rows 0..127, 2 thr per row
    const int csP0 = (tid & 1) << 1;             // pieces {0,1} / {2,3}
    float runmax = -3.4e38f;
    int   ccnt   = 0;

    for (int ct = 0; ct < KCNT / BN; ct++) {
        const int col0 = ct * BN;
        const __nv_bfloat16* ebase = g_embh + (size_t)col0 * DIM;

        float acc[2][8][4];
        #pragma unroll
        for (int mi = 0; mi < 2; mi++)
            #pragma unroll
            for (int nj = 0; nj < 8; nj++)
                #pragma unroll
                for (int q = 0; q < 4; q++) acc[mi][nj][q] = 0.f;

        // prologue: chunks 0,1 -> buffers 0,1 (each 128 rows x 64B)
        #pragma unroll
        for (int s = 0; s < 2; s++) {
            #pragma unroll
            for (int u = 0; u < 2; u++) {
                const int p = (csP0 + u) << 4;
                cp_async16(smB + s * BUFSZ + csR0 * (LDB * 2) + p,
                           reinterpret_cast<const char*>(ebase) +
                               (size_t)csR0 * DIM * 2 + s * BK * 2 + p);
            }
            cp_commit();
        }

        #pragma unroll 4
        for (int kc = 0; kc < DIM / BK; kc++) {          // 16 chunks
            if (kc + 2 < DIM / BK) {
                const int b = (kc + 2) & (NBUF - 1);
                #pragma unroll
                for (int u = 0; u < 2; u++) {
                    const int p = (csP0 + u) << 4;
                    cp_async16(smB + b * BUFSZ + csR0 * (LDB * 2) + p,
                               reinterpret_cast<const char*>(ebase) +
                                   (size_t)csR0 * DIM * 2 + (kc + 2) * BK * 2 + p);
                }
                cp_commit();
                cp_wait<2>();
            } else if (kc + 2 == DIM / BK) {
                cp_wait<1>();
            } else {
                cp_wait<0>();
            }
            __syncthreads();

            const uint32_t bufB = smB + (kc & (NBUF - 1)) * BUFSZ + bLaneOff;
            #pragma unroll
            for (int ks = 0; ks < 2; ks++) {
                uint32_t af[2][4];
                ldsm4(af[0], aBase + (kc * BK + ks * 16) * 2);
                ldsm4(af[1], aBase + (kc * BK + ks * 16) * 2 + 16 * LDA * 2);
                #pragma unroll
                for (int j = 0; j < 4; j++) {            // 4 x n16 blocks
                    uint32_t bf[4];
                    ldsm4(bf, bufB + (j * 16 * LDB + ks * 16) * 2);
                    #pragma unroll
                    for (int mi = 0; mi < 2; mi++) {
                        mma16816(acc[mi][2*j],   af[mi], bf[0], bf[2]);
                        mma16816(acc[mi][2*j+1], af[mi], bf[1], bf[3]);
                    }
                }
            }
        }
        __syncthreads();   // all reads of B bufs done before next-tile writes

        // Epilogue in two 64-col phases (Cs holds 128 x 64 f32).
        #pragma unroll
        for (int ph = 0; ph < 2; ph++) {
            if (wn == ph) {
                #pragma unroll
                for (int mi = 0; mi < 2; mi++)
                    #pragma unroll
                    for (int nj = 0; nj < 8; nj++) {
                        const int r = wm * 32 + mi * 16 + (lane >> 2);
                        const int c = nj * 8 + (lane & 3) * 2;
                        Cs[r * LDC + c]           = acc[mi][nj][0];
                        Cs[r * LDC + c + 1]       = acc[mi][nj][1];
                        Cs[(r + 8) * LDC + c]     = acc[mi][nj][2];
                        Cs[(r + 8) * LDC + c + 1] = acc[mi][nj][3];
                    }
            }
            __syncthreads();
            if (tid < BM) {
                const float4* cr = reinterpret_cast<const float4*>(Cs + tid * LDC);
                float mx = runmax;
                #pragma unroll
                for (int q = 0; q < 16; q++) {
                    const float4 v = cr[q];
                    mx = fmaxf(mx, fmaxf(fmaxf(v.x, v.y), fmaxf(v.z, v.w)));
                }
                runmax = mx;
                const float thr = mx - MARGIN;
                const int rowG = row0 + tid;
                const size_t base = (size_t)rowG * CAP;
                #pragma unroll
                for (int q = 0; q < 16; q++) {
                    const float4 v = cr[q];
                    const int kb = col0 + ph * 64 + 4 * q;
                    if (v.x >= thr) { if (ccnt < CAP) { g_cand[base+ccnt]=kb;   g_cval[base+ccnt]=v.x; } ccnt++; }
                    if (v.y >= thr) { if (ccnt < CAP) { g_cand[base+ccnt]=kb+1; g_cval[base+ccnt]=v.y; } ccnt++; }
                    if (v.z >= thr) { if (ccnt < CAP) { g_cand[base+ccnt]=kb+2; g_cval[base+ccnt]=v.z; } ccnt++; }
                    if (v.w >= thr) { if (ccnt < CAP) { g_cand[base+ccnt]=kb+3; g_cval[base+ccnt]=v.w; } ccnt++; }
                }
            }
            __syncthreads();
        }
    }
    if (tid < BM) g_cnt[row0 + tid] = ccnt;
}

// ---------------------------------------------------------------------------
// Exact rescore: warp per row, candidate per lane (validated R11). Identical
// fp32 chain; prune vs global candidate max with the same margin.
// ---------------------------------------------------------------------------
__device__ __forceinline__ void exact_score(const float4* __restrict__ zr,
                                            const float* __restrict__ emb,
                                            float an, int k,
                                            float& bv, int& bi) {
    const float4* er = reinterpret_cast<const float4*>(emb + (size_t)k * DIM);
    float acc = 0.f;
    #pragma unroll 8
    for (int q = 0; q < DIM / 4; q++) {
        const float4 a = zr[q], b = er[q];
        acc = __fmaf_rn(a.x, b.x, acc);
        acc = __fmaf_rn(a.y, b.y, acc);
        acc = __fmaf_rn(a.z, b.z, acc);
        acc = __fmaf_rn(a.w, b.w, acc);
    }
    const float t = __fadd_rn(an, g_nrm[k]);
    const float v = __fmaf_rn(-2.f, acc, t);
    if (v < bv || (v == bv && k < bi)) { bv = v; bi = k; }
}

__global__ void rescore(const float* __restrict__ z, const float* __restrict__ emb) {
    const int n    = (blockIdx.x * 256 + threadIdx.x) >> 5;
    const int lane = threadIdx.x & 31;
    if (n >= NTOK) return;
    const float an = g_nrm[KCNT + n];
    const float4* zr = reinterpret_cast<const float4*>(z + (size_t)n * DIM);
    const int cnt = g_cnt[n];
    float bv = 3.4e38f;
    int   bi = 0x7fffffff;

    if (cnt > CAP) {
        for (int k = lane; k < KCNT; k += 32)
            exact_score(zr, emb, an, k, bv, bi);
    } else {
        const size_t base = (size_t)n * CAP;
        float cmax = -3.4e38f;
        for (int s = lane; s < cnt; s += 32) cmax = fmaxf(cmax, g_cval[base + s]);
        #pragma unroll
        for (int o = 16; o; o >>= 1)
            cmax = fmaxf(cmax, __shfl_xor_sync(0xffffffffu, cmax, o));
        const float thr = cmax - MARGIN;
        for (int s = lane; s < cnt; s += 32) {
            if (g_cval[base + s] < thr) continue;
            exact_score(zr, emb, an, g_cand[base + s], bv, bi);
        }
    }
    #pragma unroll
    for (int o = 16; o; o >>= 1) {
        const float v2 = __shfl_xor_sync(0xffffffffu, bv, o);
        const int   i2 = __shfl_xor_sync(0xffffffffu, bi, o);
        if (v2 < bv || (v2 == bv && i2 < bi)) { bv = v2; bi = i2; }
    }
    if (lane == 0) g_sel[n] = bi;
}

// ---------------------------------------------------------------------------
__global__ void finalize(const float* __restrict__ z, const float* __restrict__ emb,
                         float* __restrict__ out, int N) {
    const int half = threadIdx.x >> 7;
    const int lt   = threadIdx.x & 127;
    const int n    = blockIdx.x * 2 + half;
    const int k    = g_sel[n];
    const float* zr = z + (size_t)n * DIM;
    const float* er = emb + (size_t)k * DIM;
    float* o = out + 1 + (size_t)n * DIM;
    float s = 0.f;
    #pragma unroll
    for (int j = 0; j < DIM / 128; j++) {
        const int c = lt + j * 128;
        const float zv = zr[c];
        const float dx = __fadd_rn(er[c], -zv);
        o[c] = __fadd_rn(zv, dx);
        s = __fmaf_rn(dx, dx, s);
    }
    #pragma unroll
    for (int sh = 16; sh; sh >>= 1) s += __shfl_down_sync(0xffffffffu, s, sh);
    __shared__ float ws[8];
    if ((lt & 31) == 0) ws[half * 4 + (lt >> 5)] = s;
    __syncthreads();
    if (lt == 0) {
        g_prt[n] = ws[half*4] + ws[half*4+1] + ws[half*4+2] + ws[half*4+3];
        out[1 + (size_t)N * DIM + n] = (float)k;
    }
}

__global__ void reduce_loss(float* __restrict__ out, int N) {
    __shared__ float sm[512];
    float s = 0.f;
    for (int i = threadIdx.x; i < N; i += 512) s += g_prt[i];
    sm[threadIdx.x] = s;
    __syncthreads();
    for (int o = 256; o; o >>= 1) {
        if (threadIdx.x < o) sm[threadIdx.x] += sm[threadIdx.x + o];
        __syncthreads();
    }
    if (threadIdx.x == 0) out[0] = 2.f * sm[0] / ((float)N * (float)DIM);
}

}  // namespace vq15

// ----------------------------------------------------------------------------
extern "C" void kernel_launch(void* const* d_in, const int* in_sizes, int n_in,
                              void* d_out, int out_size) {
    using namespace vq15;
    const float* z   = (const float*)d_in[0];
    const float* emb = (const float*)d_in[1];
    float* out = (float*)d_out;
    const int N = in_sizes[0] / DIM;    // 32768

    cudaFuncSetAttribute(tc_pass, cudaFuncAttributeMaxDynamicSharedMemorySize, SM_TOT);

    norms_fused<<<(KCNT + N) / 8, 256>>>(emb, z);
    prep<<<KCNT * DIM / 4 / 256, 256>>>(emb);
    tc_pass<<<N / BM, 256, SM_TOT>>>(z);
    rescore<<<N * 32 / 256, 256>>>(z, emb);
    finalize<<<N / 2, 256>>>(z, emb, out, N);
    reduce_loss<<<1, 512>>>(out, N);
}